// round 3
// baseline (speedup 1.0000x reference)
#include <cuda_runtime.h>
#include <cuda_bf16.h>
#include <math.h>

#define NN      50000
#define NE      800000
#define HID     128
#define NG      1024
#define NATOMS  100
#define NLAYERS 3

// ---------------- scratch (device globals; no allocation allowed) -------------
__device__ float g_buf0[NN * HID];   // sel 0
__device__ float g_buf1[NN * HID];   // sel 1 (h)
__device__ float g_buf2[NN * HID];   // sel 2
__device__ int   g_deg[NN + 1];
__device__ int   g_rowptr[NN + 1];
__device__ int   g_cursor[NN];
__device__ int   g_esrc[NE];
__device__ float g_ea2[NE];

__device__ __forceinline__ float* bufsel(int s) {
    return s == 0 ? g_buf0 : (s == 1 ? g_buf1 : g_buf2);
}

// ---------------- edge preprocessing ----------------------------------------
__global__ void zero_kernel() {
    int i = blockIdx.x * blockDim.x + threadIdx.x;
    if (i <= NN) g_deg[i] = 0;
    if (i < NN)  g_cursor[i] = 0;
}

__global__ void count_deg_kernel(const int* __restrict__ dst) {
    int e = blockIdx.x * blockDim.x + threadIdx.x;
    if (e < NE) atomicAdd(&g_deg[dst[e]], 1);
}

// single-block exclusive scan of g_deg[0..NN) -> g_rowptr
__global__ void scan_kernel() {
    __shared__ int warp_sums[32];
    __shared__ int s_carry;
    int tid = threadIdx.x;
    if (tid == 0) s_carry = 0;
    __syncthreads();
    for (int base = 0; base < NN; base += 1024) {
        int i = base + tid;
        int v = (i < NN) ? g_deg[i] : 0;
        int x = v;
        #pragma unroll
        for (int o = 1; o < 32; o <<= 1) {
            int y = __shfl_up_sync(0xffffffffu, x, o);
            if ((tid & 31) >= o) x += y;
        }
        if ((tid & 31) == 31) warp_sums[tid >> 5] = x;
        __syncthreads();
        if (tid < 32) {
            int w = warp_sums[tid];
            #pragma unroll
            for (int o = 1; o < 32; o <<= 1) {
                int y = __shfl_up_sync(0xffffffffu, w, o);
                if (tid >= o) w += y;
            }
            warp_sums[tid] = w;
        }
        __syncthreads();
        int incl = x + ((tid >= 32) ? warp_sums[(tid >> 5) - 1] : 0);
        int carry = s_carry;
        if (i < NN) g_rowptr[i] = carry + incl - v;   // exclusive
        __syncthreads();
        if (tid == 1023) s_carry = carry + incl;      // chunk total
        __syncthreads();
    }
    if (tid == 0) g_rowptr[NN] = s_carry;
}

__global__ void scatter_edges_kernel(const int* __restrict__ src,
                                     const int* __restrict__ dst,
                                     const float* __restrict__ ea) {
    int e = blockIdx.x * blockDim.x + threadIdx.x;
    if (e >= NE) return;
    int d = dst[e];
    int p = g_rowptr[d] + atomicAdd(&g_cursor[d], 1);
    g_esrc[p] = src[e];
    float a = ea[e];
    g_ea2[p] = a * a;
}

// ---------------- embedding gather -------------------------------------------
__global__ void embed_kernel(const int* __restrict__ x_ori,
                             const float* __restrict__ embd) {
    int i = blockIdx.x * blockDim.x + threadIdx.x;   // over NN*32 float4
    if (i >= NN * (HID / 4)) return;
    int n = i >> 5;
    int c = i & 31;
    ((float4*)g_buf0)[i] = ((const float4*)(embd + x_ori[n] * HID))[c];
}

// ---------------- GEMM + ReLU: O[n,:] = relu(X[n,:] @ W + b) ------------------
// block = 256 threads, tile = 64 rows x 128 cols, full K=128 in smem
__global__ void gemm_relu_kernel(int in_sel, int out_sel,
                                 const float* __restrict__ W,
                                 const float* __restrict__ b) {
    extern __shared__ float sm[];
    float* Ws = sm;                 // 128*128
    float* As = sm + HID * HID;     // 64*128
    const float* X = bufsel(in_sel);
    float*       O = bufsel(out_sel);
    int tid = threadIdx.x;
    int row0 = blockIdx.x * 64;

    float4* Ws4 = (float4*)Ws;
    const float4* W4 = (const float4*)W;
    #pragma unroll
    for (int i = tid; i < HID * HID / 4; i += 256) Ws4[i] = W4[i];

    float4* As4 = (float4*)As;
    #pragma unroll
    for (int i = tid; i < 64 * HID / 4; i += 256) {
        int r = i >> 5;
        int c = i & 31;
        int row = row0 + r;
        As4[i] = (row < NN) ? ((const float4*)(X + (size_t)row * HID))[c]
                            : make_float4(0.f, 0.f, 0.f, 0.f);
    }
    __syncthreads();

    int lane = tid & 31;
    int wrow = tid >> 5;   // 0..7
    float4 acc[8];
    #pragma unroll
    for (int r = 0; r < 8; r++) acc[r] = make_float4(0.f, 0.f, 0.f, 0.f);

    #pragma unroll 4
    for (int k = 0; k < HID; k++) {
        float4 w4 = Ws4[k * 32 + lane];
        #pragma unroll
        for (int r = 0; r < 8; r++) {
            float a = As[(wrow * 8 + r) * HID + k];
            acc[r].x = fmaf(a, w4.x, acc[r].x);
            acc[r].y = fmaf(a, w4.y, acc[r].y);
            acc[r].z = fmaf(a, w4.z, acc[r].z);
            acc[r].w = fmaf(a, w4.w, acc[r].w);
        }
    }

    float4 b4 = ((const float4*)b)[lane];
    #pragma unroll
    for (int r = 0; r < 8; r++) {
        int row = row0 + wrow * 8 + r;
        if (row < NN) {
            float4 o;
            o.x = fmaxf(acc[r].x + b4.x, 0.f);
            o.y = fmaxf(acc[r].y + b4.y, 0.f);
            o.z = fmaxf(acc[r].z + b4.z, 0.f);
            o.w = fmaxf(acc[r].w + b4.w, 0.f);
            ((float4*)(O + (size_t)row * HID))[lane] = o;
        }
    }
}

// ---------------- aggregation + residual + normalize -------------------------
// one block (128 threads) per node
__global__ void agg_norm_kernel(int h_sel, int x_sel, int o_sel,
                                const float* __restrict__ gamma_l,
                                const int* __restrict__ x_ori) {
    int n = blockIdx.x;
    const float* H = bufsel(h_sel);
    const float* X = bufsel(x_sel);
    float*       O = bufsel(o_sel);
    int tid = threadIdx.x;

    __shared__ float sew[128];
    __shared__ int   ssrc[128];
    __shared__ float red[4];

    int beg = g_rowptr[n];
    int end = g_rowptr[n + 1];
    float g = gamma_l[x_ori[n]];
    float gam = 1.f / (1.f + expf(-g));

    float acc = 0.f;
    for (int j0 = beg; j0 < end; j0 += 128) {
        int jn = min(128, end - j0);
        if (tid < jn) {
            ssrc[tid] = g_esrc[j0 + tid];
            sew[tid]  = expf(-gam * g_ea2[j0 + tid]);
        }
        __syncthreads();
        for (int jj = 0; jj < jn; jj++)
            acc = fmaf(sew[jj], H[(size_t)ssrc[jj] * HID + tid], acc);
        __syncthreads();
    }

    float y = acc + X[(size_t)n * HID + tid];
    float ss = y * y;
    #pragma unroll
    for (int o = 16; o > 0; o >>= 1) ss += __shfl_xor_sync(0xffffffffu, ss, o);
    if ((tid & 31) == 0) red[tid >> 5] = ss;
    __syncthreads();
    float tot = red[0] + red[1] + red[2] + red[3];
    float nrm = fmaxf(sqrtf(tot), 1e-12f);
    O[(size_t)n * HID + tid] = y / nrm;
}

// ---------------- graph pooling + head ---------------------------------------
__global__ void out_init_kernel(const float* __restrict__ wp_b, float* __restrict__ out) {
    int i = blockIdx.x * blockDim.x + threadIdx.x;
    if (i < NG) out[i] = wp_b[0];
}

__global__ void dot_scatter_kernel(int x_sel, const float* __restrict__ wp,
                                   const int* __restrict__ batch_ids,
                                   float* __restrict__ out) {
    const float* X = bufsel(x_sel);
    int warp = (blockIdx.x * blockDim.x + threadIdx.x) >> 5;
    if (warp >= NN) return;
    int lane = threadIdx.x & 31;
    float4 x4 = ((const float4*)(X + (size_t)warp * HID))[lane];
    float4 w4 = ((const float4*)wp)[lane];
    float p = x4.x * w4.x + x4.y * w4.y + x4.z * w4.z + x4.w * w4.w;
    #pragma unroll
    for (int o = 16; o > 0; o >>= 1) p += __shfl_xor_sync(0xffffffffu, p, o);
    if (lane == 0) atomicAdd(&out[batch_ids[warp]], p);
}

// ---------------- launch ------------------------------------------------------
extern "C" void kernel_launch(void* const* d_in, const int* in_sizes, int n_in,
                              void* d_out, int out_size) {
    const int*   x_ori     = (const int*)d_in[0];
    const int*   edge_idx  = (const int*)d_in[1];   // [2, NE]
    const float* edge_attr = (const float*)d_in[2]; // [NE, 1]
    const int*   batch_ids = (const int*)d_in[3];
    const float* embd_w    = (const float*)d_in[4];  // [100,128]
    const float* gamma_w   = (const float*)d_in[5];  // [3,100,1]
    const float* w_atom_W  = (const float*)d_in[6];  // [3,128,128]
    const float* w_atom_b  = (const float*)d_in[7];  // [3,128]
    const float* lin_W     = (const float*)d_in[8];  // [2,128,128]
    const float* lin_b     = (const float*)d_in[9];  // [2,128]
    const float* wp_W      = (const float*)d_in[10]; // [128,1]
    const float* wp_b      = (const float*)d_in[11]; // [1]
    float* out = (float*)d_out;

    const int* e_src = edge_idx;
    const int* e_dst = edge_idx + NE;

    static bool attr_set = false;
    if (!attr_set) {
        cudaFuncSetAttribute(gemm_relu_kernel,
                             cudaFuncAttributeMaxDynamicSharedMemorySize,
                             (HID * HID + 64 * HID) * (int)sizeof(float));
        attr_set = true;
    }
    const int GEMM_SMEM = (HID * HID + 64 * HID) * (int)sizeof(float);

    // --- edge preprocessing: CSR sorted by dst ---
    zero_kernel<<<(NN + 256) / 256, 256>>>();
    count_deg_kernel<<<(NE + 255) / 256, 256>>>(e_dst);
    scan_kernel<<<1, 1024>>>();
    scatter_edges_kernel<<<(NE + 255) / 256, 256>>>(e_src, e_dst, edge_attr);

    // --- embedding ---
    embed_kernel<<<(NN * (HID / 4) + 255) / 256, 256>>>(x_ori, embd_w);

    // --- GNN layers: ping-pong buf0 <-> buf2, h in buf1 ---
    int cur = 0;
    for (int l = 0; l < NLAYERS; l++) {
        int nxt = (cur == 0) ? 2 : 0;
        gemm_relu_kernel<<<(NN + 63) / 64, 256, GEMM_SMEM>>>(
            cur, 1, w_atom_W + (size_t)l * HID * HID, w_atom_b + (size_t)l * HID);
        agg_norm_kernel<<<NN, 128>>>(1, cur, nxt, gamma_w + (size_t)l * NATOMS, x_ori);
        cur = nxt;
    }

    // --- output MLP ---
    int o1 = (cur == 0) ? 2 : 0;
    gemm_relu_kernel<<<(NN + 63) / 64, 256, GEMM_SMEM>>>(cur, 1, lin_W, lin_b);
    gemm_relu_kernel<<<(NN + 63) / 64, 256, GEMM_SMEM>>>(
        1, o1, lin_W + (size_t)HID * HID, lin_b + HID);

    // --- pooling + head ---
    out_init_kernel<<<(NG + 255) / 256, 256>>>(wp_b, out);
    dot_scatter_kernel<<<(NN * 32 + 255) / 256, 256>>>(o1, wp_W, batch_ids, out);
}

// round 5
// speedup vs baseline: 1.2098x; 1.2098x over previous
#include <cuda_runtime.h>
#include <cuda_bf16.h>
#include <math.h>

#define NN      50000
#define NE      800000
#define HID     128
#define NG      1024
#define NATOMS  100
#define NLAYERS 3
#define WPAD    132          // 128 + 4 pad words: conflict-free LDS128 on Wt

// ---------------- scratch (device globals; no allocation allowed) -------------
__device__ float g_buf0[NN * HID];   // sel 0
__device__ float g_buf1[NN * HID];   // sel 1 (h)
__device__ float g_buf2[NN * HID];   // sel 2
__device__ int   g_deg[NN + 1];
__device__ int   g_rowptr[NN + 1];
__device__ int   g_cursor[NN];
__device__ int   g_bsum[64];
__device__ int   g_esrc[NE];
__device__ float g_ea2[NE];

__device__ __forceinline__ float* bufsel(int s) {
    return s == 0 ? g_buf0 : (s == 1 ? g_buf1 : g_buf2);
}

// packed f32x2 FMA: d = a*b + d elementwise on two fp32 lanes
__device__ __forceinline__ void ffma2(unsigned long long& d,
                                      unsigned long long a,
                                      unsigned long long b) {
    asm("fma.rn.f32x2 %0, %1, %2, %0;" : "+l"(d) : "l"(a), "l"(b));
}
__device__ __forceinline__ float2 unpack2(unsigned long long u) {
    float2 v;
    asm("mov.b64 {%0, %1}, %2;" : "=f"(v.x), "=f"(v.y) : "l"(u));
    return v;
}

// ---------------- edge preprocessing ----------------------------------------
__global__ void zero_kernel() {
    int i = blockIdx.x * blockDim.x + threadIdx.x;
    if (i <= NN) g_deg[i] = 0;
    if (i < NN)  g_cursor[i] = 0;
}

__global__ void count_deg_kernel(const int* __restrict__ dst) {
    int e = blockIdx.x * blockDim.x + threadIdx.x;
    if (e < NE) atomicAdd(&g_deg[dst[e]], 1);
}

// per-1024-chunk local exclusive scan + block sums (grid = 49)
__global__ void scan_local_kernel() {
    __shared__ int wsum[32];
    int tid = threadIdx.x;
    int i = blockIdx.x * 1024 + tid;
    int v = (i < NN) ? g_deg[i] : 0;
    int x = v;
    #pragma unroll
    for (int o = 1; o < 32; o <<= 1) {
        int y = __shfl_up_sync(0xffffffffu, x, o);
        if ((tid & 31) >= o) x += y;
    }
    if ((tid & 31) == 31) wsum[tid >> 5] = x;
    __syncthreads();
    if (tid < 32) {
        int w = wsum[tid];
        #pragma unroll
        for (int o = 1; o < 32; o <<= 1) {
            int y = __shfl_up_sync(0xffffffffu, w, o);
            if (tid >= o) w += y;
        }
        wsum[tid] = w;
    }
    __syncthreads();
    int incl = x + ((tid >= 32) ? wsum[(tid >> 5) - 1] : 0);
    if (i < NN) g_rowptr[i] = incl - v;          // local exclusive
    if (tid == 1023) g_bsum[blockIdx.x] = incl;  // chunk total
}

// scan the 49 chunk sums (1 block, 64 threads)
__global__ void scan_bsums_kernel() {
    __shared__ int w0tot;
    int tid = threadIdx.x;
    int v = (tid < 49) ? g_bsum[tid] : 0;
    int x = v;
    #pragma unroll
    for (int o = 1; o < 32; o <<= 1) {
        int y = __shfl_up_sync(0xffffffffu, x, o);
        if ((tid & 31) >= o) x += y;
    }
    if (tid == 31) w0tot = x;
    __syncthreads();
    if (tid >= 32) x += w0tot;
    if (tid < 49) g_bsum[tid] = x - v;           // exclusive
}

__global__ void scan_add_kernel() {
    int tid = threadIdx.x;
    int i = blockIdx.x * 1024 + tid;
    if (i < NN) g_rowptr[i] += g_bsum[blockIdx.x];
    if (i == NN - 1) g_rowptr[NN] = NE;
}

__global__ void scatter_edges_kernel(const int* __restrict__ src,
                                     const int* __restrict__ dst,
                                     const float* __restrict__ ea) {
    int e = blockIdx.x * blockDim.x + threadIdx.x;
    if (e >= NE) return;
    int d = dst[e];
    int p = g_rowptr[d] + atomicAdd(&g_cursor[d], 1);
    g_esrc[p] = src[e];
    float a = ea[e];
    g_ea2[p] = a * a;
}

// ---------------- embedding gather -------------------------------------------
__global__ void embed_kernel(const int* __restrict__ x_ori,
                             const float* __restrict__ embd) {
    int i = blockIdx.x * blockDim.x + threadIdx.x;   // over NN*32 float4
    if (i >= NN * (HID / 4)) return;
    int n = i >> 5;
    int c = i & 31;
    ((float4*)g_buf0)[i] = ((const float4*)(embd + x_ori[n] * HID))[c];
}

// ---------------- GEMM + ReLU via packed f32x2 --------------------------------
// block = 512 threads, tile = 64 rows x 128 cols, K=128 fully in smem.
// Wt in smem is TRANSPOSED (k-contiguous) so both MMA operands load as
// bit-packed ulonglong2 over k; f32x2 lanes hold even/odd-k partial sums.
__global__ void __launch_bounds__(512, 2)
gemm_relu_kernel(int in_sel, int out_sel,
                 const float* __restrict__ W,
                 const float* __restrict__ b) {
    extern __shared__ float sm[];
    float* Wt = sm;                  // [128 cols][WPAD]
    float* As = sm + HID * WPAD;     // [64 rows][128]
    const float* X = bufsel(in_sel);
    float*       O = bufsel(out_sel);
    int tid  = threadIdx.x;
    int lane = tid & 31;
    int wid  = tid >> 5;             // 0..15
    int row0 = blockIdx.x * 64;

    // stage W transposed: W[k*128+c] -> Wt[c*WPAD+k]
    #pragma unroll
    for (int i = tid; i < HID * HID; i += 512) {
        int k = i >> 7, c = i & 127;
        Wt[c * WPAD + k] = W[i];
    }
    // stage A rows
    #pragma unroll
    for (int i = tid; i < 64 * (HID / 4); i += 512) {
        int r = i >> 5, c = i & 31;
        int row = row0 + r;
        ((float4*)As)[i] = (row < NN) ? ((const float4*)(X + (size_t)row * HID))[c]
                                      : make_float4(0.f, 0.f, 0.f, 0.f);
    }
    __syncthreads();

    unsigned long long acc[4][4];    // [row][colgrp], f32x2 = even/odd-k partials
    #pragma unroll
    for (int r = 0; r < 4; r++)
        #pragma unroll
        for (int j = 0; j < 4; j++) acc[r][j] = 0ull;

    const int rbase = wid * 4;
    #pragma unroll 4
    for (int k4 = 0; k4 < 32; k4++) {
        ulonglong2 wv[4];
        #pragma unroll
        for (int j = 0; j < 4; j++)
            wv[j] = *(const ulonglong2*)&Wt[(lane + 32 * j) * WPAD + 4 * k4];
        #pragma unroll
        for (int r = 0; r < 4; r++) {
            ulonglong2 av = ((const ulonglong2*)As)[(rbase + r) * 32 + k4];
            #pragma unroll
            for (int j = 0; j < 4; j++) {
                ffma2(acc[r][j], av.x, wv[j].x);
                ffma2(acc[r][j], av.y, wv[j].y);
            }
        }
    }

    float bb[4];
    #pragma unroll
    for (int j = 0; j < 4; j++) bb[j] = b[lane + 32 * j];

    #pragma unroll
    for (int r = 0; r < 4; r++) {
        int row = row0 + rbase + r;
        if (row < NN) {
            #pragma unroll
            for (int j = 0; j < 4; j++) {
                float2 p = unpack2(acc[r][j]);
                float v = p.x + p.y + bb[j];
                O[(size_t)row * HID + lane + 32 * j] = fmaxf(v, 0.f);
            }
        }
    }
}

// ---------------- aggregation + residual + normalize -------------------------
// one WARP per node; thread holds 4 cols (float4); edge meta via shuffles
__global__ void agg_norm_kernel(int h_sel, int x_sel, int o_sel,
                                const float* __restrict__ gamma_l,
                                const int* __restrict__ x_ori) {
    int n = (blockIdx.x * blockDim.x + threadIdx.x) >> 5;
    int lane = threadIdx.x & 31;
    const float4* H4 = (const float4*)bufsel(h_sel);
    const float4* X4 = (const float4*)bufsel(x_sel);
    float4*       O4 = (float4*)bufsel(o_sel);

    int beg = g_rowptr[n];
    int end = g_rowptr[n + 1];
    float g = gamma_l[x_ori[n]];
    float gam = 1.f / (1.f + __expf(-g));

    float4 acc = make_float4(0.f, 0.f, 0.f, 0.f);
    for (int j0 = beg; j0 < end; j0 += 32) {
        int e = j0 + lane;
        int   s = 0;
        float w = 0.f;
        if (e < end) {
            s = g_esrc[e];
            w = __expf(-gam * g_ea2[e]);
        }
        int ne = min(32, end - j0);
        #pragma unroll 4
        for (int jj = 0; jj < ne; jj++) {
            float wj = __shfl_sync(0xffffffffu, w, jj);
            int   sj = __shfl_sync(0xffffffffu, s, jj);
            float4 hv = H4[(size_t)sj * 32 + lane];
            acc.x = fmaf(wj, hv.x, acc.x);
            acc.y = fmaf(wj, hv.y, acc.y);
            acc.z = fmaf(wj, hv.z, acc.z);
            acc.w = fmaf(wj, hv.w, acc.w);
        }
    }

    float4 xv = X4[(size_t)n * 32 + lane];
    float4 y;
    y.x = acc.x + xv.x; y.y = acc.y + xv.y;
    y.z = acc.z + xv.z; y.w = acc.w + xv.w;
    float ss = y.x * y.x + y.y * y.y + y.z * y.z + y.w * y.w;
    #pragma unroll
    for (int o = 16; o > 0; o >>= 1) ss += __shfl_xor_sync(0xffffffffu, ss, o);
    float inv = 1.f / fmaxf(sqrtf(ss), 1e-12f);
    y.x *= inv; y.y *= inv; y.z *= inv; y.w *= inv;
    O4[(size_t)n * 32 + lane] = y;
}

// ---------------- graph pooling + head ---------------------------------------
__global__ void out_init_kernel(const float* __restrict__ wp_b, float* __restrict__ out) {
    int i = blockIdx.x * blockDim.x + threadIdx.x;
    if (i < NG) out[i] = wp_b[0];
}

__global__ void dot_scatter_kernel(int x_sel, const float* __restrict__ wp,
                                   const int* __restrict__ batch_ids,
                                   float* __restrict__ out) {
    const float* X = bufsel(x_sel);
    int warp = (blockIdx.x * blockDim.x + threadIdx.x) >> 5;
    if (warp >= NN) return;
    int lane = threadIdx.x & 31;
    float4 x4 = ((const float4*)(X + (size_t)warp * HID))[lane];
    float4 w4 = ((const float4*)wp)[lane];
    float p = x4.x * w4.x + x4.y * w4.y + x4.z * w4.z + x4.w * w4.w;
    #pragma unroll
    for (int o = 16; o > 0; o >>= 1) p += __shfl_xor_sync(0xffffffffu, p, o);
    if (lane == 0) atomicAdd(&out[batch_ids[warp]], p);
}

// ---------------- launch ------------------------------------------------------
extern "C" void kernel_launch(void* const* d_in, const int* in_sizes, int n_in,
                              void* d_out, int out_size) {
    const int*   x_ori     = (const int*)d_in[0];
    const int*   edge_idx  = (const int*)d_in[1];   // [2, NE]
    const float* edge_attr = (const float*)d_in[2]; // [NE, 1]
    const int*   batch_ids = (const int*)d_in[3];
    const float* embd_w    = (const float*)d_in[4];  // [100,128]
    const float* gamma_w   = (const float*)d_in[5];  // [3,100,1]
    const float* w_atom_W  = (const float*)d_in[6];  // [3,128,128]
    const float* w_atom_b  = (const float*)d_in[7];  // [3,128]
    const float* lin_W     = (const float*)d_in[8];  // [2,128,128]
    const float* lin_b     = (const float*)d_in[9];  // [2,128]
    const float* wp_W      = (const float*)d_in[10]; // [128,1]
    const float* wp_b      = (const float*)d_in[11]; // [1]
    float* out = (float*)d_out;

    const int* e_src = edge_idx;
    const int* e_dst = edge_idx + NE;

    const int GEMM_SMEM = (HID * WPAD + 64 * HID) * (int)sizeof(float);
    static bool attr_set = false;
    if (!attr_set) {
        cudaFuncSetAttribute(gemm_relu_kernel,
                             cudaFuncAttributeMaxDynamicSharedMemorySize,
                             GEMM_SMEM);
        attr_set = true;
    }

    const int NCHUNK = (NN + 1023) / 1024;   // 49

    // --- edge preprocessing: CSR sorted by dst ---
    zero_kernel<<<(NN + 256) / 256, 256>>>();
    count_deg_kernel<<<(NE + 255) / 256, 256>>>(e_dst);
    scan_local_kernel<<<NCHUNK, 1024>>>();
    scan_bsums_kernel<<<1, 64>>>();
    scan_add_kernel<<<NCHUNK, 1024>>>();
    scatter_edges_kernel<<<(NE + 255) / 256, 256>>>(e_src, e_dst, edge_attr);

    // --- embedding ---
    embed_kernel<<<(NN * (HID / 4) + 255) / 256, 256>>>(x_ori, embd_w);

    // --- GNN layers: ping-pong buf0 <-> buf2, h in buf1 ---
    int cur = 0;
    for (int l = 0; l < NLAYERS; l++) {
        int nxt = (cur == 0) ? 2 : 0;
        gemm_relu_kernel<<<(NN + 63) / 64, 512, GEMM_SMEM>>>(
            cur, 1, w_atom_W + (size_t)l * HID * HID, w_atom_b + (size_t)l * HID);
        agg_norm_kernel<<<(NN * 32 + 255) / 256, 256>>>(
            1, cur, nxt, gamma_w + (size_t)l * NATOMS, x_ori);
        cur = nxt;
    }

    // --- output MLP ---
    int o1 = (cur == 0) ? 2 : 0;
    gemm_relu_kernel<<<(NN + 63) / 64, 512, GEMM_SMEM>>>(cur, 1, lin_W, lin_b);
    gemm_relu_kernel<<<(NN + 63) / 64, 512, GEMM_SMEM>>>(
        1, o1, lin_W + (size_t)HID * HID, lin_b + HID);

    // --- pooling + head ---
    out_init_kernel<<<(NG + 255) / 256, 256>>>(wp_b, out);
    dot_scatter_kernel<<<(NN * 32 + 255) / 256, 256>>>(o1, wp_W, batch_ids, out);
}

// round 7
// speedup vs baseline: 1.2495x; 1.0328x over previous
#include <cuda_runtime.h>
#include <cuda_bf16.h>
#include <cuda_fp16.h>
#include <math.h>

#define NN      50000
#define NE      800000
#define HID     128
#define NG      1024
#define NATOMS  100
#define NLAYERS 3
#define WPAD    132          // 128 + 4 pad words: conflict-free LDS128 on Wt

// ---------------- scratch (device globals; no allocation allowed) -------------
__device__ float  g_buf0[NN * HID];   // sel 0
__device__ float  g_buf1[NN * HID];   // sel 1
__device__ float  g_buf2[NN * HID];   // sel 2
__device__ __half g_h16[NN * HID];    // sel 3: fp16 h for edge gathers
__device__ int   g_deg[NN + 1];
__device__ int   g_rowptr[NN + 1];
__device__ int   g_cursor[NN];
__device__ int   g_bsum[64];
__device__ int   g_esrc[NE];
__device__ float g_ea2[NE];

__device__ __forceinline__ float* bufsel(int s) {
    return s == 0 ? g_buf0 : (s == 1 ? g_buf1 : g_buf2);
}

// packed f32x2 FMA: d = a*b + d elementwise on two fp32 lanes
__device__ __forceinline__ void ffma2(unsigned long long& d,
                                      unsigned long long a,
                                      unsigned long long b) {
    asm("fma.rn.f32x2 %0, %1, %2, %0;" : "+l"(d) : "l"(a), "l"(b));
}
__device__ __forceinline__ float2 unpack2(unsigned long long u) {
    float2 v;
    asm("mov.b64 {%0, %1}, %2;" : "=f"(v.x), "=f"(v.y) : "l"(u));
    return v;
}

// ---------------- embedding gather + zero init + out init ---------------------
__global__ void embed_kernel(const int* __restrict__ x_ori,
                             const float* __restrict__ embd,
                             const float* __restrict__ wp_b,
                             float* __restrict__ out) {
    int i = blockIdx.x * blockDim.x + threadIdx.x;   // over NN*32 float4
    if (i <= NN) g_deg[i] = 0;
    if (i < NN)  g_cursor[i] = 0;
    if (i < NG)  out[i] = wp_b[0];
    if (i >= NN * (HID / 4)) return;
    int n = i >> 5;
    int c = i & 31;
    ((float4*)g_buf0)[i] = ((const float4*)(embd + x_ori[n] * HID))[c];
}

// ---------------- edge preprocessing ----------------------------------------
__global__ void count_deg_kernel(const int* __restrict__ dst) {
    int e = blockIdx.x * blockDim.x + threadIdx.x;
    if (e < NE) atomicAdd(&g_deg[dst[e]], 1);
}

// per-1024-chunk local exclusive scan + block sums (grid = 49)
__global__ void scan_local_kernel() {
    __shared__ int wsum[32];
    int tid = threadIdx.x;
    int i = blockIdx.x * 1024 + tid;
    int v = (i < NN) ? g_deg[i] : 0;
    int x = v;
    #pragma unroll
    for (int o = 1; o < 32; o <<= 1) {
        int y = __shfl_up_sync(0xffffffffu, x, o);
        if ((tid & 31) >= o) x += y;
    }
    if ((tid & 31) == 31) wsum[tid >> 5] = x;
    __syncthreads();
    if (tid < 32) {
        int w = wsum[tid];
        #pragma unroll
        for (int o = 1; o < 32; o <<= 1) {
            int y = __shfl_up_sync(0xffffffffu, w, o);
            if (tid >= o) w += y;
        }
        wsum[tid] = w;
    }
    __syncthreads();
    int incl = x + ((tid >= 32) ? wsum[(tid >> 5) - 1] : 0);
    if (i < NN) g_rowptr[i] = incl - v;          // local exclusive
    if (tid == 1023) g_bsum[blockIdx.x] = incl;  // chunk total
}

// scan the 49 chunk sums (1 block, 64 threads)
__global__ void scan_bsums_kernel() {
    __shared__ int w0tot;
    int tid = threadIdx.x;
    int v = (tid < 49) ? g_bsum[tid] : 0;
    int x = v;
    #pragma unroll
    for (int o = 1; o < 32; o <<= 1) {
        int y = __shfl_up_sync(0xffffffffu, x, o);
        if ((tid & 31) >= o) x += y;
    }
    if (tid == 31) w0tot = x;
    __syncthreads();
    if (tid >= 32) x += w0tot;
    if (tid < 49) g_bsum[tid] = x - v;           // exclusive
}

__global__ void scan_add_kernel() {
    int tid = threadIdx.x;
    int i = blockIdx.x * 1024 + tid;
    if (i < NN) g_rowptr[i] += g_bsum[blockIdx.x];
    if (i == NN - 1) g_rowptr[NN] = NE;
}

__global__ void scatter_edges_kernel(const int* __restrict__ src,
                                     const int* __restrict__ dst,
                                     const float* __restrict__ ea) {
    int e = blockIdx.x * blockDim.x + threadIdx.x;
    if (e >= NE) return;
    int d = dst[e];
    int p = g_rowptr[d] + atomicAdd(&g_cursor[d], 1);
    g_esrc[p] = src[e];
    float a = ea[e];
    g_ea2[p] = a * a;
}

// ---------------- GEMM + ReLU via packed f32x2 --------------------------------
// block = 512 threads, tile = 64 rows x 128 cols, K=128 fully in smem.
// Wt in smem is TRANSPOSED (k-contiguous) so both MMA operands load as
// bit-packed ulonglong2 over k; f32x2 lanes hold even/odd-k partial sums.
// out_sel 0/1/2 -> fp32 buffers; out_sel 3 -> fp16 g_h16 (for edge gathers).
__global__ void __launch_bounds__(512, 2)
gemm_relu_kernel(int in_sel, int out_sel,
                 const float* __restrict__ W,
                 const float* __restrict__ b) {
    extern __shared__ float sm[];
    float* Wt = sm;                  // [128 cols][WPAD]
    float* As = sm + HID * WPAD;     // [64 rows][128]
    const float* X = bufsel(in_sel);
    int tid  = threadIdx.x;
    int lane = tid & 31;
    int wid  = tid >> 5;             // 0..15
    int row0 = blockIdx.x * 64;

    // stage W transposed: W[k*128+c] -> Wt[c*WPAD+k]
    #pragma unroll
    for (int i = tid; i < HID * HID; i += 512) {
        int k = i >> 7, c = i & 127;
        Wt[c * WPAD + k] = W[i];
    }
    // stage A rows
    #pragma unroll
    for (int i = tid; i < 64 * (HID / 4); i += 512) {
        int r = i >> 5, c = i & 31;
        int row = row0 + r;
        ((float4*)As)[i] = (row < NN) ? ((const float4*)(X + (size_t)row * HID))[c]
                                      : make_float4(0.f, 0.f, 0.f, 0.f);
    }
    __syncthreads();

    unsigned long long acc[4][4];    // [row][colgrp], f32x2 = even/odd-k partials
    #pragma unroll
    for (int r = 0; r < 4; r++)
        #pragma unroll
        for (int j = 0; j < 4; j++) acc[r][j] = 0ull;

    const int rbase = wid * 4;
    #pragma unroll 4
    for (int k4 = 0; k4 < 32; k4++) {
        ulonglong2 wv[4];
        #pragma unroll
        for (int j = 0; j < 4; j++)
            wv[j] = *(const ulonglong2*)&Wt[(lane + 32 * j) * WPAD + 4 * k4];
        #pragma unroll
        for (int r = 0; r < 4; r++) {
            ulonglong2 av = ((const ulonglong2*)As)[(rbase + r) * 32 + k4];
            #pragma unroll
            for (int j = 0; j < 4; j++) {
                ffma2(acc[r][j], av.x, wv[j].x);
                ffma2(acc[r][j], av.y, wv[j].y);
            }
        }
    }

    float bb[4];
    #pragma unroll
    for (int j = 0; j < 4; j++) bb[j] = b[lane + 32 * j];

    if (out_sel == 3) {
        #pragma unroll
        for (int r = 0; r < 4; r++) {
            int row = row0 + rbase + r;
            if (row < NN) {
                #pragma unroll
                for (int j = 0; j < 4; j++) {
                    float2 p = unpack2(acc[r][j]);
                    float v = fmaxf(p.x + p.y + bb[j], 0.f);
                    g_h16[(size_t)row * HID + lane + 32 * j] = __float2half(v);
                }
            }
        }
    } else {
        float* O = bufsel(out_sel);
        #pragma unroll
        for (int r = 0; r < 4; r++) {
            int row = row0 + rbase + r;
            if (row < NN) {
                #pragma unroll
                for (int j = 0; j < 4; j++) {
                    float2 p = unpack2(acc[r][j]);
                    O[(size_t)row * HID + lane + 32 * j] =
                        fmaxf(p.x + p.y + bb[j], 0.f);
                }
            }
        }
    }
}

// ---------------- aggregation + residual + normalize -------------------------
// one WARP per node; lane holds 4 adjacent cols; h gathered in fp16 (8B/lane)
__global__ void agg_norm_kernel(int x_sel, int o_sel,
                                const float* __restrict__ gamma_l,
                                const int* __restrict__ x_ori) {
    int n = (blockIdx.x * blockDim.x + threadIdx.x) >> 5;
    int lane = threadIdx.x & 31;
    const float4* X4 = (const float4*)bufsel(x_sel);
    float4*       O4 = (float4*)bufsel(o_sel);

    int beg = g_rowptr[n];
    int end = g_rowptr[n + 1];
    float g = gamma_l[x_ori[n]];
    float gam = 1.f / (1.f + __expf(-g));

    float4 acc = make_float4(0.f, 0.f, 0.f, 0.f);
    for (int j0 = beg; j0 < end; j0 += 32) {
        int e = j0 + lane;
        int   s = 0;
        float w = 0.f;
        if (e < end) {
            s = g_esrc[e];
            w = __expf(-gam * g_ea2[e]);
        }
        int ne = min(32, end - j0);
        #pragma unroll 4
        for (int jj = 0; jj < ne; jj++) {
            float wj = __shfl_sync(0xffffffffu, w, jj);
            int   sj = __shfl_sync(0xffffffffu, s, jj);
            uint2 raw = *((const uint2*)(g_h16 + (size_t)sj * HID) + lane);
            __half2 ha = *(__half2*)&raw.x;
            __half2 hb = *(__half2*)&raw.y;
            float2 fa = __half22float2(ha);
            float2 fb = __half22float2(hb);
            acc.x = fmaf(wj, fa.x, acc.x);
            acc.y = fmaf(wj, fa.y, acc.y);
            acc.z = fmaf(wj, fb.x, acc.z);
            acc.w = fmaf(wj, fb.y, acc.w);
        }
    }

    float4 xv = X4[(size_t)n * 32 + lane];
    float4 y;
    y.x = acc.x + xv.x; y.y = acc.y + xv.y;
    y.z = acc.z + xv.z; y.w = acc.w + xv.w;
    float ss = y.x * y.x + y.y * y.y + y.z * y.z + y.w * y.w;
    #pragma unroll
    for (int o = 16; o > 0; o >>= 1) ss += __shfl_xor_sync(0xffffffffu, ss, o);
    float inv = 1.f / fmaxf(sqrtf(ss), 1e-12f);
    y.x *= inv; y.y *= inv; y.z *= inv; y.w *= inv;
    O4[(size_t)n * 32 + lane] = y;
}

// ---------------- graph pooling + head ---------------------------------------
__global__ void dot_scatter_kernel(int x_sel, const float* __restrict__ wp,
                                   const int* __restrict__ batch_ids,
                                   float* __restrict__ out) {
    const float* X = bufsel(x_sel);
    int warp = (blockIdx.x * blockDim.x + threadIdx.x) >> 5;
    if (warp >= NN) return;
    int lane = threadIdx.x & 31;
    float4 x4 = ((const float4*)(X + (size_t)warp * HID))[lane];
    float4 w4 = ((const float4*)wp)[lane];
    float p = x4.x * w4.x + x4.y * w4.y + x4.z * w4.z + x4.w * w4.w;
    #pragma unroll
    for (int o = 16; o > 0; o >>= 1) p += __shfl_xor_sync(0xffffffffu, p, o);
    if (lane == 0) atomicAdd(&out[batch_ids[warp]], p);
}

// ---------------- launch ------------------------------------------------------
extern "C" void kernel_launch(void* const* d_in, const int* in_sizes, int n_in,
                              void* d_out, int out_size) {
    const int*   x_ori     = (const int*)d_in[0];
    const int*   edge_idx  = (const int*)d_in[1];   // [2, NE]
    const float* edge_attr = (const float*)d_in[2]; // [NE, 1]
    const int*   batch_ids = (const int*)d_in[3];
    const float* embd_w    = (const float*)d_in[4];  // [100,128]
    const float* gamma_w   = (const float*)d_in[5];  // [3,100,1]
    const float* w_atom_W  = (const float*)d_in[6];  // [3,128,128]
    const float* w_atom_b  = (const float*)d_in[7];  // [3,128]
    const float* lin_W     = (const float*)d_in[8];  // [2,128,128]
    const float* lin_b     = (const float*)d_in[9];  // [2,128]
    const float* wp_W      = (const float*)d_in[10]; // [128,1]
    const float* wp_b      = (const float*)d_in[11]; // [1]
    float* out = (float*)d_out;

    const int* e_src = edge_idx;
    const int* e_dst = edge_idx + NE;

    const int GEMM_SMEM = (HID * WPAD + 64 * HID) * (int)sizeof(float);
    static bool attr_set = false;
    if (!attr_set) {
        cudaFuncSetAttribute(gemm_relu_kernel,
                             cudaFuncAttributeMaxDynamicSharedMemorySize,
                             GEMM_SMEM);
        attr_set = true;
    }

    const int NCHUNK = (NN + 1023) / 1024;   // 49

    // --- embedding + zero init + out init (fused) ---
    embed_kernel<<<(NN * (HID / 4) + 255) / 256, 256>>>(x_ori, embd_w, wp_b, out);

    // --- edge preprocessing: CSR sorted by dst ---
    count_deg_kernel<<<(NE + 255) / 256, 256>>>(e_dst);
    scan_local_kernel<<<NCHUNK, 1024>>>();
    scan_bsums_kernel<<<1, 64>>>();
    scan_add_kernel<<<NCHUNK, 1024>>>();
    scatter_edges_kernel<<<(NE + 255) / 256, 256>>>(e_src, e_dst, edge_attr);

    // --- GNN layers: x ping-pong buf0 <-> buf2, h in fp16 g_h16 ---
    int cur = 0;
    for (int l = 0; l < NLAYERS; l++) {
        int nxt = (cur == 0) ? 2 : 0;
        gemm_relu_kernel<<<(NN + 63) / 64, 512, GEMM_SMEM>>>(
            cur, 3, w_atom_W + (size_t)l * HID * HID, w_atom_b + (size_t)l * HID);
        agg_norm_kernel<<<(NN * 32 + 255) / 256, 256>>>(
            cur, nxt, gamma_w + (size_t)l * NATOMS, x_ori);
        cur = nxt;
    }

    // --- output MLP (fp32 path) ---
    int o1 = (cur == 0) ? 2 : 0;
    gemm_relu_kernel<<<(NN + 63) / 64, 512, GEMM_SMEM>>>(cur, 1, lin_W, lin_b);
    gemm_relu_kernel<<<(NN + 63) / 64, 512, GEMM_SMEM>>>(
        1, o1, lin_W + (size_t)HID * HID, lin_b + HID);

    // --- pooling + head ---
    dot_scatter_kernel<<<(NN * 32 + 255) / 256, 256>>>(o1, wp_W, batch_ids, out);
}